// round 1
// baseline (speedup 1.0000x reference)
#include <cuda_runtime.h>

// ---------------- Device scratch (no allocs allowed) ----------------
#define BATCH 4096

__device__ unsigned g_w1p[20];              // 25 sign bits per filter
__device__ unsigned g_w2p[50*25];           // per (filter, tap): 20 channel sign bits
__device__ unsigned g_w3p[1024*77];         // per out-neuron: 2450 sign bits (77 words)
__device__ unsigned g_w4p[10*32];           // per out-neuron: 1024 sign bits
__device__ unsigned g_packed1[BATCH*196];   // conv2 input: 20 ch bits per 14x14 pixel
__device__ unsigned char g_a2b[BATCH*2450]; // conv2 pooled-sign bytes (flatten order c*49+pix)
__device__ unsigned g_packed2[BATCH*77];    // fc3 input bits
__device__ unsigned g_packed3[BATCH*32];    // fc4 input bits (1024)

// ---------------- Weight packing (cheap, runs every launch) ----------------
// id ranges: [0,20) w1 | [20,1270) w2 | [1270,80118) w3 | [80118,80438) w4
__global__ void pack_w_kernel(const float* __restrict__ w1, const float* __restrict__ w2,
                              const float* __restrict__ w3, const float* __restrict__ w4) {
    int id = blockIdx.x * blockDim.x + threadIdx.x;
    if (id < 20) {
        unsigned m = 0;
        #pragma unroll
        for (int t = 0; t < 25; t++) m |= (unsigned)(w1[id*25 + t] > 0.0f) << t;
        g_w1p[id] = m;
    } else if (id < 1270) {
        int idx = id - 20; int f = idx / 25, t = idx % 25;
        unsigned m = 0;
        #pragma unroll
        for (int ci = 0; ci < 20; ci++) m |= (unsigned)(w2[f*500 + ci*25 + t] > 0.0f) << ci;
        g_w2p[idx] = m;
    } else if (id < 1270 + 1024*77) {
        int idx = id - 1270; int o = idx / 77, w = idx % 77;
        unsigned m = 0; int base = w * 32;
        for (int k = 0; k < 32; k++) {
            int j = base + k;
            if (j < 2450) m |= (unsigned)(w3[o*2450 + j] > 0.0f) << k;
        }
        g_w3p[idx] = m;
    } else if (id < 1270 + 1024*77 + 320) {
        int idx = id - 1270 - 1024*77; int o = idx / 32, w = idx % 32;
        unsigned m = 0;
        #pragma unroll
        for (int k = 0; k < 32; k++) m |= (unsigned)(w4[o*1024 + w*32 + k] > 0.0f) << k;
        g_w4p[idx] = m;
    }
}

// ---------------- conv1 + relu + maxpool2 + sign -> packed channel bits ----------------
// thread per (b, pooled pixel of 14x14). Input ternary {-1,0,+1} (pad=0).
// dot = 2*popc(m & ~(p^wp)) - popc(m)
__global__ void conv1_kernel(const float* __restrict__ x, const float* __restrict__ b1) {
    __shared__ unsigned w1s[20];
    __shared__ float b1s[20];
    int tid = threadIdx.x;
    if (tid < 20) { w1s[tid] = g_w1p[tid]; b1s[tid] = b1[tid]; }
    __syncthreads();

    int id = blockIdx.x * 128 + tid;                 // exact: 6272*128 = 4096*196
    int b = id / 196, pix = id % 196;
    int py = pix / 14, px = pix % 14;
    const float* xb = x + b * 784;

    unsigned mc[36], pc[36];
    #pragma unroll
    for (int i = 0; i < 6; i++) {
        int y = py*2 - 2 + i;
        #pragma unroll
        for (int j = 0; j < 6; j++) {
            int xx = px*2 - 2 + j;
            float v = 0.0f;
            if ((unsigned)y < 28u && (unsigned)xx < 28u) v = xb[y*28 + xx];
            mc[i*6+j] = (v != 0.0f);
            pc[i*6+j] = (v > 0.0f);
        }
    }
    unsigned m0=0,m1=0,m2=0,m3=0,p0=0,p1=0,p2=0,p3=0;
    #pragma unroll
    for (int ky = 0; ky < 5; ky++)
    #pragma unroll
    for (int kx = 0; kx < 5; kx++) {
        int t = ky*5 + kx;
        m0 |= mc[ky*6+kx]       << t;  p0 |= pc[ky*6+kx]       << t;
        m1 |= mc[ky*6+kx+1]     << t;  p1 |= pc[ky*6+kx+1]     << t;
        m2 |= mc[(ky+1)*6+kx]   << t;  p2 |= pc[(ky+1)*6+kx]   << t;
        m3 |= mc[(ky+1)*6+kx+1] << t;  p3 |= pc[(ky+1)*6+kx+1] << t;
    }
    int pm0 = __popc(m0), pm1 = __popc(m1), pm2 = __popc(m2), pm3 = __popc(m3);

    unsigned word = 0;
    #pragma unroll
    for (int c = 0; c < 20; c++) {
        unsigned wp = w1s[c];
        int d0 = 2*__popc(m0 & ~(p0 ^ wp)) - pm0;
        int d1 = 2*__popc(m1 & ~(p1 ^ wp)) - pm1;
        int d2 = 2*__popc(m2 & ~(p2 ^ wp)) - pm2;
        int d3 = 2*__popc(m3 & ~(p3 ^ wp)) - pm3;
        int mx = max(max(d0, d1), max(d2, d3));
        if ((float)mx + b1s[c] > 0.0f) word |= 1u << c;
    }
    g_packed1[id] = word;
}

// ---------------- conv2 + relu + maxpool2 + sign -> bytes in flatten order ----------------
// thread per (b, pooled pixel of 7x7). Inputs {0,1} packed 20/word.
// dot = 2*P - S, S filter-independent.
__global__ void conv2_kernel(const float* __restrict__ b2) {
    __shared__ unsigned w2s[1250];
    __shared__ float b2s[50];
    int tid = threadIdx.x;
    for (int t = tid; t < 1250; t += 128) w2s[t] = g_w2p[t];
    if (tid < 50) b2s[tid] = b2[tid];
    __syncthreads();

    int id = blockIdx.x * 128 + tid;                 // exact: 1568*128 = 4096*49
    int b = id / 49, pix = id % 49;
    int py = pix / 7, px = pix % 7;
    const unsigned* inb = g_packed1 + b * 196;

    unsigned iw[36]; int pcv[36];
    #pragma unroll
    for (int i = 0; i < 6; i++) {
        int y = py*2 - 2 + i;
        #pragma unroll
        for (int j = 0; j < 6; j++) {
            int xx = px*2 - 2 + j;
            unsigned v = 0u;
            if ((unsigned)y < 14u && (unsigned)xx < 14u) v = inb[y*14 + xx];
            iw[i*6+j] = v; pcv[i*6+j] = __popc(v);
        }
    }
    int S0=0,S1=0,S2=0,S3=0;
    #pragma unroll
    for (int ky = 0; ky < 5; ky++)
    #pragma unroll
    for (int kx = 0; kx < 5; kx++) {
        S0 += pcv[ky*6+kx];     S1 += pcv[ky*6+kx+1];
        S2 += pcv[(ky+1)*6+kx]; S3 += pcv[(ky+1)*6+kx+1];
    }

    unsigned char* outp = g_a2b + b*2450 + pix;
    for (int f = 0; f < 50; f++) {
        int P0=0,P1=0,P2=0,P3=0;
        #pragma unroll
        for (int ky = 0; ky < 5; ky++)
        #pragma unroll
        for (int kx = 0; kx < 5; kx++) {
            unsigned w = w2s[f*25 + ky*5 + kx];
            P0 += __popc(iw[ky*6+kx]       & w);
            P1 += __popc(iw[ky*6+kx+1]     & w);
            P2 += __popc(iw[(ky+1)*6+kx]   & w);
            P3 += __popc(iw[(ky+1)*6+kx+1] & w);
        }
        int mx = max(max(2*P0 - S0, 2*P1 - S1), max(2*P2 - S2, 2*P3 - S3));
        outp[f*49] = ((float)mx + b2s[f] > 0.0f) ? 1 : 0;
    }
}

// ---------------- pack conv2 output bytes into 77-word bit rows ----------------
__global__ void packA2_kernel() {
    int id = blockIdx.x * 128 + threadIdx.x;         // exact: 2464*128 = 4096*77
    int b = id / 77, w = id % 77;
    const unsigned char* src = g_a2b + b*2450 + w*32;
    int n = min(32, 2450 - w*32);
    unsigned word = 0;
    for (int k = 0; k < n; k++) word |= ((unsigned)src[k]) << k;
    g_packed2[id] = word;
}

// ---------------- fc3: [4096,2450]x[1024,2450]^T, relu+sign -> packed bits ----------------
// block: 128 out-neurons x 8 batch rows; w3 word reused 8x from registers.
__global__ void fc3_kernel(const float* __restrict__ b3) {
    __shared__ unsigned sa[8*77];
    __shared__ int sna[8];
    int tid = threadIdx.x;
    int b0 = blockIdx.y * 8;
    for (int t = tid; t < 8*77; t += 128)
        sa[t] = g_packed2[(b0 + t/77)*77 + (t % 77)];
    __syncthreads();
    if (tid < 8) {
        int s = 0;
        for (int i = 0; i < 77; i++) s += __popc(sa[tid*77 + i]);
        sna[tid] = s;
    }
    __syncthreads();

    int o = blockIdx.x * 128 + tid;                  // 8 blocks x 128 = 1024
    const unsigned* wrow = g_w3p + o*77;
    int cnt[8];
    #pragma unroll
    for (int bb = 0; bb < 8; bb++) cnt[bb] = 0;
    for (int i = 0; i < 77; i++) {
        unsigned w = wrow[i];
        #pragma unroll
        for (int bb = 0; bb < 8; bb++) cnt[bb] += __popc(sa[bb*77 + i] & w);
    }
    float bias = b3[o];
    int widx = o >> 5;
    #pragma unroll
    for (int bb = 0; bb < 8; bb++) {
        float val = (float)(2*cnt[bb] - sna[bb]) + bias;
        unsigned word = __ballot_sync(0xffffffffu, val > 0.0f);
        if ((tid & 31) == 0) g_packed3[(b0 + bb)*32 + widx] = word;
    }
}

// ---------------- fc4: [4096,1024]x[10,1024]^T -> float out ----------------
__global__ void fc4_kernel(const float* __restrict__ b4, float* __restrict__ out) {
    int b = blockIdx.x * 128 + threadIdx.x;          // 32*128 = 4096
    unsigned a[32]; int na = 0;
    #pragma unroll
    for (int i = 0; i < 32; i++) { a[i] = g_packed3[b*32 + i]; na += __popc(a[i]); }
    #pragma unroll
    for (int k = 0; k < 10; k++) {
        int cnt = 0;
        #pragma unroll
        for (int i = 0; i < 32; i++) cnt += __popc(a[i] & g_w4p[k*32 + i]);
        out[b*10 + k] = (float)(2*cnt - na) + b4[k];
    }
}

// ---------------- launch ----------------
extern "C" void kernel_launch(void* const* d_in, const int* in_sizes, int n_in,
                              void* d_out, int out_size) {
    const float* x  = (const float*)d_in[0];
    const float* w1 = (const float*)d_in[1];
    const float* b1 = (const float*)d_in[2];
    const float* w2 = (const float*)d_in[3];
    const float* b2 = (const float*)d_in[4];
    const float* w3 = (const float*)d_in[5];
    const float* b3 = (const float*)d_in[6];
    const float* w4 = (const float*)d_in[7];
    const float* b4 = (const float*)d_in[8];
    float* out = (float*)d_out;

    pack_w_kernel<<<629, 128>>>(w1, w2, w3, w4);     // 80438 items
    conv1_kernel<<<6272, 128>>>(x, b1);              // 4096*196
    conv2_kernel<<<1568, 128>>>(b2);                 // 4096*49
    packA2_kernel<<<2464, 128>>>();                  // 4096*77
    fc3_kernel<<<dim3(8, 512), 128>>>(b3);           // 1024 x (4096/8)
    fc4_kernel<<<32, 128>>>(b4, out);                // 4096
}

// round 2
// speedup vs baseline: 1.3253x; 1.3253x over previous
#include <cuda_runtime.h>

#define BATCH 4096

// ---------------- Device scratch ----------------
__device__ unsigned g_w1p[20];                         // 25 sign bits per filter
__device__ __align__(16) unsigned g_w2q[50*16];        // per filter: 500-bit window layout (p = t*20+c)
__device__ __align__(16) unsigned g_w3p[1024*80];      // per out-neuron: 2450 bits, order j' = pix*50+c, padded to 80 words
__device__ unsigned g_w4p[10*32];                      // per out-neuron: 1024 sign bits
__device__ unsigned g_packed1[BATCH*196];              // conv2 input: 20 ch bits per 14x14 pixel
__device__ __align__(16) unsigned g_packed2[BATCH*80]; // fc3 input bits (order pix*50+c), padded
__device__ unsigned g_packed3[BATCH*32];               // fc4 input bits (1024)

// ---------------- Weight packing ----------------
// ranges: [0,20) w1 | [20,820) w2q | [820,82740) w3 | [82740,83060) w4
__global__ void pack_w_kernel(const float* __restrict__ w1, const float* __restrict__ w2,
                              const float* __restrict__ w3, const float* __restrict__ w4) {
    int id = blockIdx.x * blockDim.x + threadIdx.x;
    if (id < 20) {
        unsigned m = 0;
        #pragma unroll
        for (int t = 0; t < 25; t++) m |= (unsigned)(w1[id*25 + t] > 0.0f) << t;
        g_w1p[id] = m;
    } else if (id < 820) {
        int idx = id - 20; int f = idx / 16, w = idx % 16;
        unsigned m = 0;
        for (int k = 0; k < 32; k++) {
            int p = w*32 + k;
            if (p < 500) {
                int t = p / 20, c = p % 20;
                m |= (unsigned)(w2[f*500 + c*25 + t] > 0.0f) << k;
            }
        }
        g_w2q[idx] = m;
    } else if (id < 82740) {
        int idx = id - 820; int o = idx / 80, w = idx % 80;
        unsigned m = 0;
        for (int k = 0; k < 32; k++) {
            int j = w*32 + k;                  // permuted index
            if (j < 2450) {
                int pix = j / 50, c = j % 50;  // orig flat index = c*49 + pix
                m |= (unsigned)(w3[o*2450 + c*49 + pix] > 0.0f) << k;
            }
        }
        g_w3p[idx] = m;
    } else if (id < 83060) {
        int idx = id - 82740; int o = idx / 32, w = idx % 32;
        unsigned m = 0;
        #pragma unroll
        for (int k = 0; k < 32; k++) m |= (unsigned)(w4[o*1024 + w*32 + k] > 0.0f) << k;
        g_w4p[idx] = m;
    }
}

// ---------------- conv1 + relu + maxpool2 + sign -> packed channel bits ----------------
__global__ void conv1_kernel(const float* __restrict__ x, const float* __restrict__ b1) {
    __shared__ unsigned w1s[20];
    __shared__ float b1s[20];
    int tid = threadIdx.x;
    if (tid < 20) { w1s[tid] = g_w1p[tid]; b1s[tid] = b1[tid]; }
    __syncthreads();

    int id = blockIdx.x * 128 + tid;                 // 6272*128 = 4096*196
    if (id < BATCH*80) g_packed2[id] = 0;            // zero fc3-input rows for conv2's atomicOr
    int b = id / 196, pix = id % 196;
    int py = pix / 14, px = pix % 14;
    const float* xb = x + b * 784;

    unsigned mc[36], pc[36];
    #pragma unroll
    for (int i = 0; i < 6; i++) {
        int y = py*2 - 2 + i;
        #pragma unroll
        for (int j = 0; j < 6; j++) {
            int xx = px*2 - 2 + j;
            float v = 0.0f;
            if ((unsigned)y < 28u && (unsigned)xx < 28u) v = xb[y*28 + xx];
            mc[i*6+j] = (v != 0.0f);
            pc[i*6+j] = (v > 0.0f);
        }
    }
    unsigned m0=0,m1=0,m2=0,m3=0,p0=0,p1=0,p2=0,p3=0;
    #pragma unroll
    for (int ky = 0; ky < 5; ky++)
    #pragma unroll
    for (int kx = 0; kx < 5; kx++) {
        int t = ky*5 + kx;
        m0 |= mc[ky*6+kx]       << t;  p0 |= pc[ky*6+kx]       << t;
        m1 |= mc[ky*6+kx+1]     << t;  p1 |= pc[ky*6+kx+1]     << t;
        m2 |= mc[(ky+1)*6+kx]   << t;  p2 |= pc[(ky+1)*6+kx]   << t;
        m3 |= mc[(ky+1)*6+kx+1] << t;  p3 |= pc[(ky+1)*6+kx+1] << t;
    }
    int pm0 = __popc(m0), pm1 = __popc(m1), pm2 = __popc(m2), pm3 = __popc(m3);

    unsigned word = 0;
    #pragma unroll
    for (int c = 0; c < 20; c++) {
        unsigned wp = w1s[c];
        int d0 = 2*__popc(m0 & ~(p0 ^ wp)) - pm0;
        int d1 = 2*__popc(m1 & ~(p1 ^ wp)) - pm1;
        int d2 = 2*__popc(m2 & ~(p2 ^ wp)) - pm2;
        int d3 = 2*__popc(m3 & ~(p3 ^ wp)) - pm3;
        int mx = max(max(d0, d1), max(d2, d3));
        if ((float)mx + b1s[c] > 0.0f) word |= 1u << c;
    }
    g_packed1[id] = word;
}

// ---------------- conv2: dense 512-bit window packing ----------------
template<int BASE>
__device__ __forceinline__ void pack_window(const unsigned iw[36], unsigned W[16]) {
    unsigned long long acc = 0; int off = 0; int wi = 0;
    #pragma unroll
    for (int ky = 0; ky < 5; ky++) {
        #pragma unroll
        for (int kx = 0; kx < 5; kx++) {
            unsigned long long v = iw[BASE + ky*6 + kx];
            acc |= v << off;
            off += 20;
            if (off >= 32) { W[wi++] = (unsigned)acc; acc >>= 32; off -= 32; }
        }
    }
    W[wi] = (unsigned)acc;
}

__global__ void __launch_bounds__(128) conv2_kernel(const float* __restrict__ b2) {
    __shared__ __align__(16) unsigned sw[50*16];
    __shared__ float b2s[50];
    int tid = threadIdx.x;
    for (int t = tid; t < 800; t += 128) sw[t] = g_w2q[t];
    if (tid < 50) b2s[tid] = b2[tid];
    __syncthreads();

    int id = blockIdx.x * 128 + tid;                 // 1568*128 = 4096*49
    int b = id / 49, pix = id % 49;
    int py = pix / 7, px = pix % 7;
    const unsigned* inb = g_packed1 + b * 196;

    unsigned iw[36];
    #pragma unroll
    for (int i = 0; i < 6; i++) {
        int y = py*2 - 2 + i;
        #pragma unroll
        for (int j = 0; j < 6; j++) {
            int xx = px*2 - 2 + j;
            unsigned v = 0u;
            if ((unsigned)y < 14u && (unsigned)xx < 14u) v = inb[y*14 + xx];
            iw[i*6+j] = v;
        }
    }

    unsigned W0[16], W1[16], W2[16], W3[16];
    pack_window<0>(iw, W0);   // window (0,0)
    pack_window<1>(iw, W1);   // window (0,1)
    pack_window<6>(iw, W2);   // window (1,0)
    pack_window<7>(iw, W3);   // window (1,1)

    int S0=0,S1=0,S2=0,S3=0;
    #pragma unroll
    for (int j = 0; j < 16; j++) {
        S0 += __popc(W0[j]); S1 += __popc(W1[j]);
        S2 += __popc(W2[j]); S3 += __popc(W3[j]);
    }

    unsigned long long bits = 0ull;
    for (int f = 0; f < 50; f++) {
        const uint4* fp = (const uint4*)&sw[f*16];
        int P0=0,P1=0,P2=0,P3=0;
        #pragma unroll
        for (int q = 0; q < 4; q++) {
            uint4 w = fp[q];
            unsigned fw[4] = {w.x, w.y, w.z, w.w};
            #pragma unroll
            for (int k = 0; k < 4; k++) {
                int j = q*4 + k;
                P0 += __popc(W0[j] & fw[k]);
                P1 += __popc(W1[j] & fw[k]);
                P2 += __popc(W2[j] & fw[k]);
                P3 += __popc(W3[j] & fw[k]);
            }
        }
        int mx = max(max(2*P0 - S0, 2*P1 - S1), max(2*P2 - S2, 2*P3 - S3));
        bits |= (unsigned long long)((float)mx + b2s[f] > 0.0f) << f;
    }

    // scatter 50 contiguous bits into the fc3 bit row at offset pix*50
    unsigned* row = g_packed2 + b * 80;
    int base = pix * 50;
    int w0 = base >> 5, sh = base & 31;
    unsigned long long lo = bits << sh;
    atomicOr(&row[w0],     (unsigned)lo);
    atomicOr(&row[w0 + 1], (unsigned)(lo >> 32));
    if (sh >= 15) atomicOr(&row[w0 + 2], (unsigned)(bits >> (64 - sh)));
}

// ---------------- fc3: [4096,2450] x [1024,2450]^T, relu+sign -> packed bits ----------------
__global__ void fc3_kernel(const float* __restrict__ b3) {
    __shared__ __align__(16) unsigned sa[8*80];
    __shared__ int sna[8];
    int tid = threadIdx.x;
    int b0 = blockIdx.y * 8;
    for (int t = tid; t < 8*80; t += 128)
        sa[t] = g_packed2[(b0 + t/80)*80 + (t % 80)];
    __syncthreads();
    if (tid < 8) {
        int s = 0;
        for (int i = 0; i < 80; i++) s += __popc(sa[tid*80 + i]);
        sna[tid] = s;
    }
    __syncthreads();

    int o = blockIdx.x * 128 + tid;                  // 8 x 128 = 1024
    const uint4* wrow = (const uint4*)(g_w3p + o*80);
    int cnt[8];
    #pragma unroll
    for (int bb = 0; bb < 8; bb++) cnt[bb] = 0;
    #pragma unroll 4
    for (int i = 0; i < 20; i++) {
        uint4 w = wrow[i];
        #pragma unroll
        for (int bb = 0; bb < 8; bb++) {
            uint4 a = *(const uint4*)&sa[bb*80 + i*4];
            cnt[bb] += __popc(a.x & w.x) + __popc(a.y & w.y)
                     + __popc(a.z & w.z) + __popc(a.w & w.w);
        }
    }
    float bias = b3[o];
    int widx = o >> 5;
    #pragma unroll
    for (int bb = 0; bb < 8; bb++) {
        float val = (float)(2*cnt[bb] - sna[bb]) + bias;
        unsigned word = __ballot_sync(0xffffffffu, val > 0.0f);
        if ((tid & 31) == 0) g_packed3[(b0 + bb)*32 + widx] = word;
    }
}

// ---------------- fc4: [4096,1024] x [10,1024]^T -> float out ----------------
__global__ void fc4_kernel(const float* __restrict__ b4, float* __restrict__ out) {
    int b = blockIdx.x * 128 + threadIdx.x;          // 32*128 = 4096
    unsigned a[32]; int na = 0;
    #pragma unroll
    for (int i = 0; i < 32; i++) { a[i] = g_packed3[b*32 + i]; na += __popc(a[i]); }
    #pragma unroll
    for (int k = 0; k < 10; k++) {
        int cnt = 0;
        #pragma unroll
        for (int i = 0; i < 32; i++) cnt += __popc(a[i] & g_w4p[k*32 + i]);
        out[b*10 + k] = (float)(2*cnt - na) + b4[k];
    }
}

// ---------------- launch ----------------
extern "C" void kernel_launch(void* const* d_in, const int* in_sizes, int n_in,
                              void* d_out, int out_size) {
    const float* x  = (const float*)d_in[0];
    const float* w1 = (const float*)d_in[1];
    const float* b1 = (const float*)d_in[2];
    const float* w2 = (const float*)d_in[3];
    const float* b2 = (const float*)d_in[4];
    const float* w3 = (const float*)d_in[5];
    const float* b3 = (const float*)d_in[6];
    const float* w4 = (const float*)d_in[7];
    const float* b4 = (const float*)d_in[8];
    float* out = (float*)d_out;

    pack_w_kernel<<<649, 128>>>(w1, w2, w3, w4);     // 83060 items
    conv1_kernel<<<6272, 128>>>(x, b1);              // 4096*196 (+ zeroes g_packed2)
    conv2_kernel<<<1568, 128>>>(b2);                 // 4096*49
    fc3_kernel<<<dim3(8, 512), 128>>>(b3);           // 1024 x (4096/8)
    fc4_kernel<<<32, 128>>>(b4, out);                // 4096
}

// round 4
// speedup vs baseline: 1.4095x; 1.0636x over previous
#include <cuda_runtime.h>

#define BATCH 4096

// ---------------- Device scratch ----------------
__device__ unsigned g_w1p[20];                         // 25 sign bits per filter
__device__ __align__(16) unsigned g_w2q[50*16];        // per filter: 500-bit window layout (p = t*20+c)
__device__ __align__(16) unsigned g_w3p[1024*80];      // per out-neuron: 2450 bits, order j' = pix*50+c, pad 80
__device__ unsigned g_w4p[10*32];                      // per out-neuron: 1024 sign bits
__device__ unsigned g_xrow[BATCH*64];                  // per image: [0..31]=mask rows, [32..63]=sign rows (bit xx+2)
__device__ unsigned g_packed1[BATCH*196];              // conv2 input: 20 ch bits per 14x14 pixel
__device__ __align__(16) unsigned g_packed2[BATCH*80]; // fc3 input bits (order pix*50+c), padded
__device__ unsigned g_packed3[BATCH*32];               // fc4 input bits (1024)

// ---------------- Weight packing ----------------
// ranges: [0,20) w1 | [20,820) w2q | [820,82740) w3 | [82740,83060) w4
__global__ void pack_w_kernel(const float* __restrict__ w1, const float* __restrict__ w2,
                              const float* __restrict__ w3, const float* __restrict__ w4) {
    int id = blockIdx.x * blockDim.x + threadIdx.x;
    if (id < 20) {
        unsigned m = 0;
        #pragma unroll
        for (int t = 0; t < 25; t++) m |= (unsigned)(w1[id*25 + t] > 0.0f) << t;
        g_w1p[id] = m;
    } else if (id < 820) {
        int idx = id - 20; int f = idx / 16, w = idx % 16;
        unsigned m = 0;
        for (int k = 0; k < 32; k++) {
            int p = w*32 + k;
            if (p < 500) {
                int t = p / 20, c = p % 20;
                m |= (unsigned)(w2[f*500 + c*25 + t] > 0.0f) << k;
            }
        }
        g_w2q[idx] = m;
    } else if (id < 82740) {
        int idx = id - 820; int o = idx / 80, w = idx % 80;
        unsigned m = 0;
        for (int k = 0; k < 32; k++) {
            int j = w*32 + k;
            if (j < 2450) {
                int pix = j / 50, c = j % 50;  // orig flat index = c*49 + pix
                m |= (unsigned)(w3[o*2450 + c*49 + pix] > 0.0f) << k;
            }
        }
        g_w3p[idx] = m;
    } else if (id < 83060) {
        int idx = id - 82740; int o = idx / 32, w = idx % 32;
        unsigned m = 0;
        #pragma unroll
        for (int k = 0; k < 32; k++) m |= (unsigned)(w4[o*1024 + w*32 + k] > 0.0f) << k;
        g_w4p[idx] = m;
    }
}

// ---------------- pack x into per-row mask/sign bit words ----------------
// row word bit (xx+2) = pixel xx; rows 0,1,30,31 are zero pad (y = r-2)
__global__ void pack_xrow_kernel(const float* __restrict__ x) {
    int id = blockIdx.x * 128 + threadIdx.x;          // 1024*128 = 4096*32
    int b = id >> 5, r = id & 31;
    unsigned m = 0, p = 0;
    if (r >= 2 && r < 30) {
        const float* row = x + b*784 + (r-2)*28;
        #pragma unroll
        for (int xx = 0; xx < 28; xx++) {
            float v = row[xx];
            m |= (unsigned)(v != 0.0f) << (xx + 2);
            p |= (unsigned)(v > 0.0f)  << (xx + 2);
        }
    }
    g_xrow[b*64 + r]      = m;
    g_xrow[b*64 + 32 + r] = p;
}

// ---------------- conv1 + relu + maxpool2 + sign -> packed channel bits ----------------
__global__ void __launch_bounds__(128) conv1_kernel(const float* __restrict__ b1) {
    __shared__ unsigned w1s[20];
    __shared__ float b1s[20];
    int tid = threadIdx.x;
    if (tid < 20) { w1s[tid] = g_w1p[tid]; b1s[tid] = b1[tid]; }
    __syncthreads();

    int id = blockIdx.x * 128 + tid;                 // 6272*128 = 4096*196
    if (id < BATCH*80) g_packed2[id] = 0;            // zero fc3-input rows for conv2's atomicOr
    int b = id / 196, pix = id % 196;
    int py = pix / 14, px = pix % 14;
    const unsigned* xr = g_xrow + b*64;

    unsigned mr[6], pr[6];
    #pragma unroll
    for (int i = 0; i < 6; i++) { mr[i] = xr[2*py + i]; pr[i] = xr[32 + 2*py + i]; }

    unsigned M[4], P[4]; int pm[4];
    #pragma unroll
    for (int dy = 0; dy < 2; dy++)
    #pragma unroll
    for (int dx = 0; dx < 2; dx++) {
        int sh = 2*px + dx;
        unsigned m = 0, p = 0;
        #pragma unroll
        for (int ky = 0; ky < 5; ky++) {
            m |= ((mr[dy + ky] >> sh) & 31u) << (5*ky);
            p |= ((pr[dy + ky] >> sh) & 31u) << (5*ky);
        }
        int w = dy*2 + dx;
        M[w] = m; P[w] = p; pm[w] = __popc(m);
    }

    unsigned word = 0;
    #pragma unroll
    for (int c = 0; c < 20; c++) {
        unsigned wp = w1s[c];
        int d0 = 2*__popc(M[0] & ~(P[0] ^ wp)) - pm[0];
        int d1 = 2*__popc(M[1] & ~(P[1] ^ wp)) - pm[1];
        int d2 = 2*__popc(M[2] & ~(P[2] ^ wp)) - pm[2];
        int d3 = 2*__popc(M[3] & ~(P[3] ^ wp)) - pm[3];
        int mx = max(max(d0, d1), max(d2, d3));
        if ((float)mx + b1s[c] > 0.0f) word |= 1u << c;
    }
    g_packed1[id] = word;
}

// ---------------- conv2: dense 512-bit window packing ----------------
template<int BASE>
__device__ __forceinline__ void pack_window(const unsigned iw[36], unsigned W[16]) {
    unsigned long long acc = 0; int off = 0; int wi = 0;
    #pragma unroll
    for (int ky = 0; ky < 5; ky++) {
        #pragma unroll
        for (int kx = 0; kx < 5; kx++) {
            unsigned long long v = iw[BASE + ky*6 + kx];
            acc |= v << off;
            off += 20;
            if (off >= 32) { W[wi++] = (unsigned)acc; acc >>= 32; off -= 32; }
        }
    }
    W[wi] = (unsigned)acc;
}

__global__ void __launch_bounds__(128) conv2_kernel(const float* __restrict__ b2) {
    __shared__ __align__(16) unsigned sw[50*16];
    __shared__ float b2s[50];
    int tid = threadIdx.x;
    for (int t = tid; t < 800; t += 128) sw[t] = g_w2q[t];
    if (tid < 50) b2s[tid] = b2[tid];
    __syncthreads();

    int id = blockIdx.x * 128 + tid;                 // 1568*128 = 4096*49
    int b = id / 49, pix = id % 49;
    int py = pix / 7, px = pix % 7;
    const unsigned* inb = g_packed1 + b * 196;

    unsigned iw[36];
    #pragma unroll
    for (int i = 0; i < 6; i++) {
        int y = py*2 - 2 + i;
        #pragma unroll
        for (int j = 0; j < 6; j++) {
            int xx = px*2 - 2 + j;
            unsigned v = 0u;
            if ((unsigned)y < 14u && (unsigned)xx < 14u) v = inb[y*14 + xx];
            iw[i*6+j] = v;
        }
    }

    unsigned W0[16], W1[16], W2[16], W3[16];
    pack_window<0>(iw, W0);
    pack_window<1>(iw, W1);
    pack_window<6>(iw, W2);
    pack_window<7>(iw, W3);

    int S0=0,S1=0,S2=0,S3=0;
    #pragma unroll
    for (int j = 0; j < 16; j++) {
        S0 += __popc(W0[j]); S1 += __popc(W1[j]);
        S2 += __popc(W2[j]); S3 += __popc(W3[j]);
    }

    unsigned long long bits = 0ull;
    for (int f = 0; f < 50; f++) {
        const uint4* fp = (const uint4*)&sw[f*16];
        int P0=0,P1=0,P2=0,P3=0;
        #pragma unroll
        for (int q = 0; q < 4; q++) {
            uint4 w = fp[q];
            unsigned fw[4] = {w.x, w.y, w.z, w.w};
            #pragma unroll
            for (int k = 0; k < 4; k++) {
                int j = q*4 + k;
                P0 += __popc(W0[j] & fw[k]);
                P1 += __popc(W1[j] & fw[k]);
                P2 += __popc(W2[j] & fw[k]);
                P3 += __popc(W3[j] & fw[k]);
            }
        }
        int mx = max(max(2*P0 - S0, 2*P1 - S1), max(2*P2 - S2, 2*P3 - S3));
        bits |= (unsigned long long)((float)mx + b2s[f] > 0.0f) << f;
    }

    unsigned* row = g_packed2 + b * 80;
    int base = pix * 50;
    int w0 = base >> 5, sh = base & 31;
    unsigned long long lo = bits << sh;
    atomicOr(&row[w0],     (unsigned)lo);
    atomicOr(&row[w0 + 1], (unsigned)(lo >> 32));
    if (sh >= 15) atomicOr(&row[w0 + 2], (unsigned)(bits >> (64 - sh)));
}

// ---------------- fc3: register-tiled 4 outputs x 8 batches per thread ----------------
__global__ void __launch_bounds__(128) fc3_kernel(const float* __restrict__ b3) {
    __shared__ __align__(16) unsigned sa[8*80];
    __shared__ int sna[8];
    int tid = threadIdx.x;
    int b0 = blockIdx.y * 8;
    // 8 rows contiguous = 640 words = 160 uint4; 128 threads -> strided loop (FIX)
    for (int t = tid; t < 160; t += 128)
        ((uint4*)sa)[t] = ((const uint4*)(g_packed2 + b0*80))[t];
    __syncthreads();
    if (tid < 8) {
        int s = 0;
        #pragma unroll 8
        for (int i = 0; i < 80; i++) s += __popc(sa[tid*80 + i]);
        sna[tid] = s;
    }
    __syncthreads();

    int obase = blockIdx.x * 512 + tid;              // outputs obase + 128*j, j=0..3
    const uint4* wr0 = (const uint4*)(g_w3p + (obase        )*80);
    const uint4* wr1 = (const uint4*)(g_w3p + (obase + 128  )*80);
    const uint4* wr2 = (const uint4*)(g_w3p + (obase + 256  )*80);
    const uint4* wr3 = (const uint4*)(g_w3p + (obase + 384  )*80);

    int cnt[4][8];
    #pragma unroll
    for (int j = 0; j < 4; j++)
        #pragma unroll
        for (int bb = 0; bb < 8; bb++) cnt[j][bb] = 0;

    #pragma unroll 2
    for (int i = 0; i < 20; i++) {
        uint4 w[4] = {wr0[i], wr1[i], wr2[i], wr3[i]};
        #pragma unroll
        for (int bb = 0; bb < 8; bb++) {
            uint4 a = *(const uint4*)&sa[bb*80 + i*4];
            #pragma unroll
            for (int j = 0; j < 4; j++) {
                cnt[j][bb] += __popc(a.x & w[j].x) + __popc(a.y & w[j].y)
                            + __popc(a.z & w[j].z) + __popc(a.w & w[j].w);
            }
        }
    }

    #pragma unroll
    for (int j = 0; j < 4; j++) {
        int o = obase + 128*j;
        float bias = b3[o];
        int widx = o >> 5;
        #pragma unroll
        for (int bb = 0; bb < 8; bb++) {
            float val = (float)(2*cnt[j][bb] - sna[bb]) + bias;
            unsigned word = __ballot_sync(0xffffffffu, val > 0.0f);
            if ((tid & 31) == 0) g_packed3[(b0 + bb)*32 + widx] = word;
        }
    }
}

// ---------------- fc4: [4096,1024] x [10,1024]^T -> float out ----------------
__global__ void __launch_bounds__(128) fc4_kernel(const float* __restrict__ b4, float* __restrict__ out) {
    __shared__ unsigned w4s[10*32];
    __shared__ float b4s[10];
    int tid = threadIdx.x;
    for (int t = tid; t < 320; t += 128) w4s[t] = g_w4p[t];
    if (tid < 10) b4s[tid] = b4[tid];
    __syncthreads();

    int b = blockIdx.x * 128 + tid;                  // 32*128 = 4096
    unsigned a[32]; int na = 0;
    #pragma unroll
    for (int i = 0; i < 32; i++) { a[i] = g_packed3[b*32 + i]; na += __popc(a[i]); }
    #pragma unroll
    for (int k = 0; k < 10; k++) {
        int cnt = 0;
        #pragma unroll
        for (int i = 0; i < 32; i++) cnt += __popc(a[i] & w4s[k*32 + i]);
        out[b*10 + k] = (float)(2*cnt - na) + b4s[k];
    }
}

// ---------------- launch ----------------
extern "C" void kernel_launch(void* const* d_in, const int* in_sizes, int n_in,
                              void* d_out, int out_size) {
    const float* x  = (const float*)d_in[0];
    const float* w1 = (const float*)d_in[1];
    const float* b1 = (const float*)d_in[2];
    const float* w2 = (const float*)d_in[3];
    const float* b2 = (const float*)d_in[4];
    const float* w3 = (const float*)d_in[5];
    const float* b3 = (const float*)d_in[6];
    const float* w4 = (const float*)d_in[7];
    const float* b4 = (const float*)d_in[8];
    float* out = (float*)d_out;

    pack_w_kernel<<<649, 128>>>(w1, w2, w3, w4);     // 83060 items
    pack_xrow_kernel<<<1024, 128>>>(x);              // 4096*32 rows
    conv1_kernel<<<6272, 128>>>(b1);                 // 4096*196 (+ zeroes g_packed2)
    conv2_kernel<<<1568, 128>>>(b2);                 // 4096*49
    fc3_kernel<<<dim3(2, 512), 128>>>(b3);           // 1024 outs x (4096/8) batch groups
    fc4_kernel<<<32, 128>>>(b4, out);                // 4096
}